// round 9
// baseline (speedup 1.0000x reference)
#include <cuda_runtime.h>
#include <cuda_fp16.h>
#include <cstdint>
#include <cstddef>

// ---------------- problem constants ----------------
#define TOKENS 8192
#define IN_F   4096
#define OUT_F  11008
#define NGROUP 32          // group size 128

// ---------------- GEMM tiling ----------------
#define BM 128
#define BN 128
#define BK 64              // fp16 per k-chunk (128B rows, SW128)
#define STAGES 3
#define NKCH (IN_F / BK)   // 64
#define NSEG (NKCH / 2)    // 32 segments of 2 chunks (fp16 inner accum span K=128)
#define MT (TOKENS / BM)   // 64
#define NT (OUT_F / BN)    // 86

#define A_BYTES (BM * BK * 2)            // 16384
#define B_BYTES (BN * BK * 2)            // 16384
#define STAGE_BYTES (A_BYTES + B_BYTES)  // 32768
#define SMEM_TOTAL (STAGES * STAGE_BYTES)  // 98304 -> 2 CTAs/SM

#define SWZ(o) ((o) ^ (((o) >> 3) & 0x70))

// ---------------- scratch ----------------
__device__ __half g_xh[(size_t)TOKENS * IN_F];  // dequantized activations
__device__ __half g_wh[(size_t)OUT_F * IN_F];   // dequantized weights

// ---------------- PTX helpers (baseline-arch only) ----------------
__device__ __forceinline__ uint32_t smem_u32(const void* p) {
    uint32_t a;
    asm("{ .reg .u64 t; cvta.to.shared.u64 t, %1; cvt.u32.u64 %0, t; }" : "=r"(a) : "l"(p));
    return a;
}
__device__ __forceinline__ void cp_async16(uint32_t s, const void* g) {
    asm volatile("cp.async.cg.shared.global [%0], [%1], 16;" :: "r"(s), "l"(g) : "memory");
}
__device__ __forceinline__ void cp_commit() {
    asm volatile("cp.async.commit_group;" ::: "memory");
}
template <int N>
__device__ __forceinline__ void cp_wait() {
    asm volatile("cp.async.wait_group %0;" :: "n"(N) : "memory");
}
__device__ __forceinline__ void ldsm_x4(uint32_t* r, uint32_t addr) {
    asm volatile("ldmatrix.sync.aligned.m8n8.x4.shared.b16 {%0,%1,%2,%3}, [%4];"
                 : "=r"(r[0]), "=r"(r[1]), "=r"(r[2]), "=r"(r[3]) : "r"(addr));
}
// fp16-accumulator HMMA: accumulate form (D==C in regs)
__device__ __forceinline__ void mma16816_h_acc(uint32_t* d, const uint32_t* a, uint32_t b0,
                                               uint32_t b1) {
    asm volatile(
        "mma.sync.aligned.m16n8k16.row.col.f16.f16.f16.f16 "
        "{%0,%1}, {%2,%3,%4,%5}, {%6,%7}, {%0,%1};"
        : "+r"(d[0]), "+r"(d[1])
        : "r"(a[0]), "r"(a[1]), "r"(a[2]), "r"(a[3]), "r"(b0), "r"(b1));
}
// init form: C = 0 (starts a fresh fp16 inner-accumulation segment)
__device__ __forceinline__ void mma16816_h_init(uint32_t* d, const uint32_t* a, uint32_t b0,
                                                uint32_t b1) {
    asm volatile(
        "mma.sync.aligned.m16n8k16.row.col.f16.f16.f16.f16 "
        "{%0,%1}, {%2,%3,%4,%5}, {%6,%7}, {%8,%8};"
        : "=r"(d[0]), "=r"(d[1])
        : "r"(a[0]), "r"(a[1]), "r"(a[2]), "r"(a[3]), "r"(b0), "r"(b1), "r"(0u));
}

// ---------------- dequant prepasses ----------------
union Pack8 { __half2 h[2]; uint2 u; };

__global__ __launch_bounds__(256) void dequant_x_kernel(const float4* __restrict__ x,
                                                        const float* __restrict__ sx) {
    int row = blockIdx.x;
    float s = sx[row];
    const float4* xr = x + (size_t)row * (IN_F / 4);
    uint2* outr = reinterpret_cast<uint2*>(g_xh + (size_t)row * IN_F);
#pragma unroll
    for (int it = 0; it < IN_F / 4 / 256; it++) {
        int c = it * 256 + threadIdx.x;
        float4 v = xr[c];
        Pack8 p;
        p.h[0] = __floats2half2_rn(v.x * s, v.y * s);
        p.h[1] = __floats2half2_rn(v.z * s, v.w * s);
        outr[c] = p.u;
    }
}

__global__ __launch_bounds__(256) void dequant_w_kernel(const float4* __restrict__ w,
                                                        const float* __restrict__ ws,
                                                        const float* __restrict__ wo) {
    int row = blockIdx.x;
    const float4* wr = w + (size_t)row * (IN_F / 4);
    const float* wsr = ws + (size_t)row * NGROUP;
    const float* wor = wo + (size_t)row * NGROUP;
    uint2* outr = reinterpret_cast<uint2*>(g_wh + (size_t)row * IN_F);
#pragma unroll
    for (int it = 0; it < IN_F / 4 / 256; it++) {
        int c = it * 256 + threadIdx.x;
        int g = c >> 5;  // 32 float4 = 128 elements per group
        float s = wsr[g];
        float o = wor[g];
        float4 v = wr[c];
        Pack8 p;
        p.h[0] = __floats2half2_rn((v.x - o) * s, (v.y - o) * s);
        p.h[1] = __floats2half2_rn((v.z - o) * s, (v.w - o) * s);
        outr[c] = p.u;
    }
}

// ---------------- multistage HMMA GEMM, fp16 inner accumulation ----------------
__device__ __forceinline__ void load_stage(uint32_t sb, const __half* __restrict__ a_base,
                                           const __half* __restrict__ b_base, int j, int slot,
                                           int tid) {
    const __half* as = a_base + j * BK;
    const __half* bs = b_base + j * BK;
    uint32_t a_smem = sb + slot * STAGE_BYTES;
    uint32_t b_smem = a_smem + A_BYTES;
#pragma unroll
    for (int i = 0; i < 8; i++) {  // A: 128 rows x 8 chunks of 16B
        int cid = i * 128 + tid;
        int row = cid >> 3, col = cid & 7;
        cp_async16(a_smem + SWZ(row * 128 + col * 16), as + (size_t)row * IN_F + col * 8);
    }
#pragma unroll
    for (int i = 0; i < 8; i++) {  // B: 128 rows x 8 chunks of 16B
        int cid = i * 128 + tid;
        int row = cid >> 3, col = cid & 7;
        cp_async16(b_smem + SWZ(row * 128 + col * 16), bs + (size_t)row * IN_F + col * 8);
    }
}

// One 64-wide k chunk: pipeline bookkeeping + 4 k16 MMA steps into fp16 accumulators.
// INIT: first chunk of a segment (fp16 C starts at zero via init-form mma).
template <bool INIT>
__device__ __forceinline__ void do_chunk(int ks, uint32_t (&ch)[4][8][2], uint32_t sb,
                                         const __half* a_base, const __half* b_base, int tid,
                                         int wm, int wn, int lr, int hh16) {
    int slot = ks % STAGES;
    cp_wait<STAGES - 2>();  // stage `slot` resident
    __syncthreads();        // recycled slot's last reads (prev chunk) complete

    int nxt = ks + STAGES - 1;
    if (nxt < NKCH) load_stage(sb, a_base, b_base, nxt, nxt % STAGES, tid);
    cp_commit();            // empty-group commit in tail keeps wait counting uniform

    uint32_t stA = sb + slot * STAGE_BYTES;
    uint32_t stB = stA + A_BYTES;
#pragma unroll
    for (int kk = 0; kk < BK / 16; kk++) {
        uint32_t a[16], b[16];
        int kb = kk * 32 + hh16;
#pragma unroll
        for (int mf = 0; mf < 4; mf++) {
            int row = wm + mf * 16 + lr;
            ldsm_x4(&a[mf * 4], stA + SWZ(row * 128 + kb));
        }
#pragma unroll
        for (int bi = 0; bi < 4; bi++) {
            int row = wn + bi * 16 + lr;
            ldsm_x4(&b[bi * 4], stB + SWZ(row * 128 + kb));
        }
#pragma unroll
        for (int mf = 0; mf < 4; mf++)
#pragma unroll
            for (int nf = 0; nf < 8; nf++) {
                const uint32_t* bb = &b[(nf >> 1) * 4];
                if (INIT && kk == 0)
                    mma16816_h_init(ch[mf][nf], &a[mf * 4], bb[nf & 1], bb[2 + (nf & 1)]);
                else
                    mma16816_h_acc(ch[mf][nf], &a[mf * 4], bb[nf & 1], bb[2 + (nf & 1)]);
            }
    }
}

__global__ __launch_bounds__(128, 2) void qlinear_gemm_kernel(float* __restrict__ C) {
    extern __shared__ char smem[];
    uint32_t sb = smem_u32(smem);
    int tid = threadIdx.x;
    int lid = tid & 31, wid = tid >> 5;
    int wm = (wid >> 1) * 64;   // warp M offset: 0 / 64
    int wn = (wid & 1) * 64;    // warp N offset: 0 / 64
    int lr = lid & 15;
    int hh16 = (lid >> 4) * 16;
    int bid = blockIdx.x;
    int mt = bid % MT;
    int nt = bid / MT;          // M fastest: A set L2-resident, B shared within wave

    const __half* a_base = g_xh + (size_t)mt * BM * IN_F;
    const __half* b_base = g_wh + (size_t)nt * BN * IN_F;

    // prologue: fill STAGES-1 stages (one commit group per chunk)
#pragma unroll
    for (int j = 0; j < STAGES - 1; j++) {
        load_stage(sb, a_base, b_base, j, j, tid);
        cp_commit();
    }

    float c[4][8][4];
#pragma unroll
    for (int i = 0; i < 4; i++)
#pragma unroll
        for (int j = 0; j < 8; j++)
#pragma unroll
            for (int q = 0; q < 4; q++) c[i][j][q] = 0.0f;

    uint32_t ch[4][8][2];  // fp16 accumulators (half2 pairs), re-seeded per segment

#pragma unroll 1
    for (int seg = 0; seg < NSEG; seg++) {
        do_chunk<true>(seg * 2, ch, sb, a_base, b_base, tid, wm, wn, lr, hh16);
        do_chunk<false>(seg * 2 + 1, ch, sb, a_base, b_base, tid, wm, wn, lr, hh16);
        // promote segment's fp16 partials into fp32 accumulators
#pragma unroll
        for (int mf = 0; mf < 4; mf++)
#pragma unroll
            for (int nf = 0; nf < 8; nf++) {
                float2 f0 = __half22float2(*reinterpret_cast<__half2*>(&ch[mf][nf][0]));
                float2 f1 = __half22float2(*reinterpret_cast<__half2*>(&ch[mf][nf][1]));
                c[mf][nf][0] += f0.x;
                c[mf][nf][1] += f0.y;
                c[mf][nf][2] += f1.x;
                c[mf][nf][3] += f1.y;
            }
    }

    // epilogue: fp32 accumulators -> gmem
    int gid = lid >> 2, ctid = lid & 3;
    float* Cb = C + (size_t)(mt * BM + wm + gid) * OUT_F + nt * BN + wn + ctid * 2;
#pragma unroll
    for (int mf = 0; mf < 4; mf++) {
#pragma unroll
        for (int nf = 0; nf < 8; nf++) {
            float2 v0 = make_float2(c[mf][nf][0], c[mf][nf][1]);
            float2 v1 = make_float2(c[mf][nf][2], c[mf][nf][3]);
            *reinterpret_cast<float2*>(Cb + (size_t)(mf * 16) * OUT_F + nf * 8) = v0;
            *reinterpret_cast<float2*>(Cb + (size_t)(mf * 16 + 8) * OUT_F + nf * 8) = v1;
        }
    }
}

// ---------------- launch ----------------
extern "C" void kernel_launch(void* const* d_in, const int* in_sizes, int n_in,
                              void* d_out, int out_size) {
    (void)in_sizes; (void)n_in; (void)out_size;
    const float* x  = (const float*)d_in[0];
    const float* sx = (const float*)d_in[1];
    const float* w  = (const float*)d_in[2];
    const float* ws = (const float*)d_in[3];
    const float* wo = (const float*)d_in[4];
    float* out = (float*)d_out;

    cudaFuncSetAttribute(qlinear_gemm_kernel, cudaFuncAttributeMaxDynamicSharedMemorySize,
                         SMEM_TOTAL);

    dequant_x_kernel<<<TOKENS, 256>>>((const float4*)x, sx);
    dequant_w_kernel<<<OUT_F, 256>>>((const float4*)w, ws, wo);
    qlinear_gemm_kernel<<<MT * NT, 128, SMEM_TOTAL>>>(out);
}

// round 10
// speedup vs baseline: 1.0463x; 1.0463x over previous
#include <cuda_runtime.h>
#include <cuda_fp16.h>
#include <cstdint>
#include <cstddef>

// ---------------- problem constants ----------------
#define TOKENS 8192
#define IN_F   4096
#define OUT_F  11008
#define NGROUP 32          // group size 128

// ---------------- GEMM tiling ----------------
#define BM 256
#define BN 128
#define BK 64              // fp16 per k-chunk (128B rows, SW128)
#define STAGES 3
#define NKCH (IN_F / BK)   // 64
#define MT (TOKENS / BM)   // 32
#define NT (OUT_F / BN)    // 86

#define A_BYTES (BM * BK * 2)            // 32768
#define B_BYTES (BN * BK * 2)            // 16384
#define STAGE_BYTES (A_BYTES + B_BYTES)  // 49152
#define SMEM_TOTAL (STAGES * STAGE_BYTES)  // 147456

#define SWZ(o) ((o) ^ (((o) >> 3) & 0x70))

// ---------------- scratch ----------------
__device__ __half g_xh[(size_t)TOKENS * IN_F];  // dequantized activations
__device__ __half g_wh[(size_t)OUT_F * IN_F];   // dequantized weights

// ---------------- PTX helpers (baseline-arch only) ----------------
__device__ __forceinline__ uint32_t smem_u32(const void* p) {
    uint32_t a;
    asm("{ .reg .u64 t; cvta.to.shared.u64 t, %1; cvt.u32.u64 %0, t; }" : "=r"(a) : "l"(p));
    return a;
}
__device__ __forceinline__ void cp_async16(uint32_t s, const void* g) {
    asm volatile("cp.async.cg.shared.global [%0], [%1], 16;" :: "r"(s), "l"(g) : "memory");
}
__device__ __forceinline__ void cp_commit() {
    asm volatile("cp.async.commit_group;" ::: "memory");
}
template <int N>
__device__ __forceinline__ void cp_wait() {
    asm volatile("cp.async.wait_group %0;" :: "n"(N) : "memory");
}
__device__ __forceinline__ void ldsm_x4(uint32_t* r, uint32_t addr) {
    asm volatile("ldmatrix.sync.aligned.m8n8.x4.shared.b16 {%0,%1,%2,%3}, [%4];"
                 : "=r"(r[0]), "=r"(r[1]), "=r"(r[2]), "=r"(r[3]) : "r"(addr));
}
__device__ __forceinline__ void mma16816(float* c, const uint32_t* a, uint32_t b0, uint32_t b1) {
    asm volatile(
        "mma.sync.aligned.m16n8k16.row.col.f32.f16.f16.f32 "
        "{%0,%1,%2,%3}, {%4,%5,%6,%7}, {%8,%9}, {%0,%1,%2,%3};"
        : "+f"(c[0]), "+f"(c[1]), "+f"(c[2]), "+f"(c[3])
        : "r"(a[0]), "r"(a[1]), "r"(a[2]), "r"(a[3]), "r"(b0), "r"(b1));
}

// ---------------- dequant prepasses ----------------
union Pack8 { __half2 h[2]; uint2 u; };

__global__ __launch_bounds__(256) void dequant_x_kernel(const float4* __restrict__ x,
                                                        const float* __restrict__ sx) {
    int row = blockIdx.x;
    float s = sx[row];
    const float4* xr = x + (size_t)row * (IN_F / 4);
    uint2* outr = reinterpret_cast<uint2*>(g_xh + (size_t)row * IN_F);
#pragma unroll
    for (int it = 0; it < IN_F / 4 / 256; it++) {
        int c = it * 256 + threadIdx.x;
        float4 v = xr[c];
        Pack8 p;
        p.h[0] = __floats2half2_rn(v.x * s, v.y * s);
        p.h[1] = __floats2half2_rn(v.z * s, v.w * s);
        outr[c] = p.u;
    }
}

__global__ __launch_bounds__(256) void dequant_w_kernel(const float4* __restrict__ w,
                                                        const float* __restrict__ ws,
                                                        const float* __restrict__ wo) {
    int row = blockIdx.x;
    const float4* wr = w + (size_t)row * (IN_F / 4);
    const float* wsr = ws + (size_t)row * NGROUP;
    const float* wor = wo + (size_t)row * NGROUP;
    uint2* outr = reinterpret_cast<uint2*>(g_wh + (size_t)row * IN_F);
#pragma unroll
    for (int it = 0; it < IN_F / 4 / 256; it++) {
        int c = it * 256 + threadIdx.x;
        int g = c >> 5;  // 32 float4 = 128 elements per group
        float s = wsr[g];
        float o = wor[g];
        float4 v = wr[c];
        Pack8 p;
        p.h[0] = __floats2half2_rn((v.x - o) * s, (v.y - o) * s);
        p.h[1] = __floats2half2_rn((v.z - o) * s, (v.w - o) * s);
        outr[c] = p.u;
    }
}

// ---------------- multistage HMMA GEMM: 512 thr, 16 warps 8x2, warp tile 32x64 ----------------
__device__ __forceinline__ void load_stage(uint32_t sb, const __half* __restrict__ a_base,
                                           const __half* __restrict__ b_base, int j, int slot,
                                           int tid) {
    const __half* as = a_base + j * BK;
    const __half* bs = b_base + j * BK;
    uint32_t a_smem = sb + slot * STAGE_BYTES;
    uint32_t b_smem = a_smem + A_BYTES;
#pragma unroll
    for (int i = 0; i < 4; i++) {  // A: 256 rows x 8 chunks of 16B = 2048
        int cid = i * 512 + tid;
        int row = cid >> 3, col = cid & 7;
        cp_async16(a_smem + SWZ(row * 128 + col * 16), as + (size_t)row * IN_F + col * 8);
    }
#pragma unroll
    for (int i = 0; i < 2; i++) {  // B: 128 rows x 8 chunks of 16B = 1024
        int cid = i * 512 + tid;
        int row = cid >> 3, col = cid & 7;
        cp_async16(b_smem + SWZ(row * 128 + col * 16), bs + (size_t)row * IN_F + col * 8);
    }
}

__global__ __launch_bounds__(512, 1) void qlinear_gemm_kernel(float* __restrict__ C) {
    extern __shared__ char smem[];
    uint32_t sb = smem_u32(smem);
    int tid = threadIdx.x;
    int lid = tid & 31, wid = tid >> 5;
    int wm = (wid >> 1) * 32;   // warp M offset: 0..224 (8 slots)
    int wn = (wid & 1) * 64;    // warp N offset: 0 / 64
    int lr = lid & 15;
    int hh16 = (lid >> 4) * 16;
    int bid = blockIdx.x;
    int mt = bid % MT;
    int nt = bid / MT;          // M fastest: B tile shared by 32 consecutive CTAs via L2

    const __half* a_base = g_xh + (size_t)mt * BM * IN_F;
    const __half* b_base = g_wh + (size_t)nt * BN * IN_F;

    // prologue: fill STAGES-1 stages (one commit group per chunk)
#pragma unroll
    for (int j = 0; j < STAGES - 1; j++) {
        load_stage(sb, a_base, b_base, j, j, tid);
        cp_commit();
    }

    float c[2][8][4];
#pragma unroll
    for (int i = 0; i < 2; i++)
#pragma unroll
        for (int j = 0; j < 8; j++)
#pragma unroll
            for (int q = 0; q < 4; q++) c[i][j][q] = 0.0f;

#pragma unroll 1
    for (int ks = 0; ks < NKCH; ks++) {
        int slot = ks % STAGES;
        cp_wait<STAGES - 2>();  // stage `slot` resident
        __syncthreads();        // recycled slot's last reads (prev chunk) complete

        int nxt = ks + STAGES - 1;
        if (nxt < NKCH) load_stage(sb, a_base, b_base, nxt, nxt % STAGES, tid);
        cp_commit();            // empty-group commit in tail keeps wait counting uniform

        uint32_t stA = sb + slot * STAGE_BYTES;
        uint32_t stB = stA + A_BYTES;
#pragma unroll
        for (int kk = 0; kk < BK / 16; kk++) {
            uint32_t a[8], b[16];
            int kb = kk * 32 + hh16;
#pragma unroll
            for (int mf = 0; mf < 2; mf++) {
                int row = wm + mf * 16 + lr;
                ldsm_x4(&a[mf * 4], stA + SWZ(row * 128 + kb));
            }
#pragma unroll
            for (int bi = 0; bi < 4; bi++) {
                int row = wn + bi * 16 + lr;
                ldsm_x4(&b[bi * 4], stB + SWZ(row * 128 + kb));
            }
#pragma unroll
            for (int mf = 0; mf < 2; mf++)
#pragma unroll
                for (int nf = 0; nf < 8; nf++) {
                    const uint32_t* bb = &b[(nf >> 1) * 4];
                    mma16816(c[mf][nf], &a[mf * 4], bb[nf & 1], bb[2 + (nf & 1)]);
                }
        }
    }

    // epilogue: register accumulators -> gmem fp32
    int gid = lid >> 2, ctid = lid & 3;
    float* Cb = C + (size_t)(mt * BM + wm + gid) * OUT_F + nt * BN + wn + ctid * 2;
#pragma unroll
    for (int mf = 0; mf < 2; mf++) {
#pragma unroll
        for (int nf = 0; nf < 8; nf++) {
            float2 v0 = make_float2(c[mf][nf][0], c[mf][nf][1]);
            float2 v1 = make_float2(c[mf][nf][2], c[mf][nf][3]);
            *reinterpret_cast<float2*>(Cb + (size_t)(mf * 16) * OUT_F + nf * 8) = v0;
            *reinterpret_cast<float2*>(Cb + (size_t)(mf * 16 + 8) * OUT_F + nf * 8) = v1;
        }
    }
}

// ---------------- launch ----------------
extern "C" void kernel_launch(void* const* d_in, const int* in_sizes, int n_in,
                              void* d_out, int out_size) {
    (void)in_sizes; (void)n_in; (void)out_size;
    const float* x  = (const float*)d_in[0];
    const float* sx = (const float*)d_in[1];
    const float* w  = (const float*)d_in[2];
    const float* ws = (const float*)d_in[3];
    const float* wo = (const float*)d_in[4];
    float* out = (float*)d_out;

    cudaFuncSetAttribute(qlinear_gemm_kernel, cudaFuncAttributeMaxDynamicSharedMemorySize,
                         SMEM_TOTAL);

    dequant_x_kernel<<<TOKENS, 256>>>((const float4*)x, sx);
    dequant_w_kernel<<<OUT_F, 256>>>((const float4*)w, ws, wo);
    qlinear_gemm_kernel<<<MT * NT, 512, SMEM_TOTAL>>>(out);
}

// round 11
// speedup vs baseline: 1.1258x; 1.0760x over previous
#include <cuda_runtime.h>
#include <cuda_fp16.h>
#include <cstdint>
#include <cstddef>

// ---------------- problem constants ----------------
#define TOKENS 8192
#define IN_F   4096
#define OUT_F  11008
#define NGROUP 32          // group size 128

// ---------------- GEMM tiling ----------------
#define BM 128
#define BN 128
#define BK 64              // fp16 per k-chunk (128B rows, SW128)
#define STAGES 3
#define NKCH (IN_F / BK)   // 64
#define NSTEP (NKCH * 4)   // 256 k16 steps
#define MT (TOKENS / BM)   // 64
#define NT (OUT_F / BN)    // 86

#define A_BYTES (BM * BK * 2)            // 16384
#define B_BYTES (BN * BK * 2)            // 16384
#define STAGE_BYTES (A_BYTES + B_BYTES)  // 32768
#define SMEM_TOTAL (STAGES * STAGE_BYTES)  // 98304 -> 2 CTAs/SM

#define SWZ(o) ((o) ^ (((o) >> 3) & 0x70))

// ---------------- scratch ----------------
__device__ __half g_xh[(size_t)TOKENS * IN_F];  // dequantized activations
__device__ __half g_wh[(size_t)OUT_F * IN_F];   // dequantized weights

// ---------------- PTX helpers (baseline-arch only) ----------------
__device__ __forceinline__ uint32_t smem_u32(const void* p) {
    uint32_t a;
    asm("{ .reg .u64 t; cvta.to.shared.u64 t, %1; cvt.u32.u64 %0, t; }" : "=r"(a) : "l"(p));
    return a;
}
__device__ __forceinline__ void cp_async16(uint32_t s, const void* g) {
    asm volatile("cp.async.cg.shared.global [%0], [%1], 16;" :: "r"(s), "l"(g) : "memory");
}
__device__ __forceinline__ void cp_commit() {
    asm volatile("cp.async.commit_group;" ::: "memory");
}
template <int N>
__device__ __forceinline__ void cp_wait() {
    asm volatile("cp.async.wait_group %0;" :: "n"(N) : "memory");
}
__device__ __forceinline__ void ldsm_x4(uint32_t* r, uint32_t addr) {
    asm volatile("ldmatrix.sync.aligned.m8n8.x4.shared.b16 {%0,%1,%2,%3}, [%4];"
                 : "=r"(r[0]), "=r"(r[1]), "=r"(r[2]), "=r"(r[3]) : "r"(addr));
}
__device__ __forceinline__ void mma16816(float* c, const uint32_t* a, uint32_t b0, uint32_t b1) {
    asm volatile(
        "mma.sync.aligned.m16n8k16.row.col.f32.f16.f16.f32 "
        "{%0,%1,%2,%3}, {%4,%5,%6,%7}, {%8,%9}, {%0,%1,%2,%3};"
        : "+f"(c[0]), "+f"(c[1]), "+f"(c[2]), "+f"(c[3])
        : "r"(a[0]), "r"(a[1]), "r"(a[2]), "r"(a[3]), "r"(b0), "r"(b1));
}

// ---------------- dequant prepasses ----------------
union Pack8 { __half2 h[2]; uint2 u; };

__global__ __launch_bounds__(256) void dequant_x_kernel(const float4* __restrict__ x,
                                                        const float* __restrict__ sx) {
    int row = blockIdx.x;
    float s = sx[row];
    const float4* xr = x + (size_t)row * (IN_F / 4);
    uint2* outr = reinterpret_cast<uint2*>(g_xh + (size_t)row * IN_F);
#pragma unroll
    for (int it = 0; it < IN_F / 4 / 256; it++) {
        int c = it * 256 + threadIdx.x;
        float4 v = xr[c];
        Pack8 p;
        p.h[0] = __floats2half2_rn(v.x * s, v.y * s);
        p.h[1] = __floats2half2_rn(v.z * s, v.w * s);
        outr[c] = p.u;
    }
}

__global__ __launch_bounds__(256) void dequant_w_kernel(const float4* __restrict__ w,
                                                        const float* __restrict__ ws,
                                                        const float* __restrict__ wo) {
    int row = blockIdx.x;
    const float4* wr = w + (size_t)row * (IN_F / 4);
    const float* wsr = ws + (size_t)row * NGROUP;
    const float* wor = wo + (size_t)row * NGROUP;
    uint2* outr = reinterpret_cast<uint2*>(g_wh + (size_t)row * IN_F);
#pragma unroll
    for (int it = 0; it < IN_F / 4 / 256; it++) {
        int c = it * 256 + threadIdx.x;
        int g = c >> 5;  // 32 float4 = 128 elements per group
        float s = wsr[g];
        float o = wor[g];
        float4 v = wr[c];
        Pack8 p;
        p.h[0] = __floats2half2_rn((v.x - o) * s, (v.y - o) * s);
        p.h[1] = __floats2half2_rn((v.z - o) * s, (v.w - o) * s);
        outr[c] = p.u;
    }
}

// ---------------- multistage HMMA GEMM: R7 shape + k16 fragment double-buffer ----------------
__device__ __forceinline__ void load_stage(uint32_t sb, const __half* __restrict__ a_base,
                                           const __half* __restrict__ b_base, int j, int slot,
                                           int tid) {
    const __half* as = a_base + j * BK;
    const __half* bs = b_base + j * BK;
    uint32_t a_smem = sb + slot * STAGE_BYTES;
    uint32_t b_smem = a_smem + A_BYTES;
#pragma unroll
    for (int i = 0; i < 4; i++) {  // A: 128 rows x 8 chunks of 16B = 1024
        int cid = i * 256 + tid;
        int row = cid >> 3, col = cid & 7;
        cp_async16(a_smem + SWZ(row * 128 + col * 16), as + (size_t)row * IN_F + col * 8);
    }
#pragma unroll
    for (int i = 0; i < 4; i++) {  // B: 128 rows x 8 chunks of 16B = 1024
        int cid = i * 256 + tid;
        int row = cid >> 3, col = cid & 7;
        cp_async16(b_smem + SWZ(row * 128 + col * 16), bs + (size_t)row * IN_F + col * 8);
    }
}

// Fetch fragments for k16 step `stp`. On chunk boundary: wait for the chunk's
// stage, barrier for slot-reuse safety (the recycled slot's last ldsm reads were
// issued one step earlier and land ~600cyc before the refill writes arrive),
// then issue the cp.async refill for chunk+STAGES-1 before any ldsm.
__device__ __forceinline__ void fetch_step(int stp, uint32_t (&af)[16], uint32_t (&bf)[8],
                                           uint32_t sb, const __half* a_base,
                                           const __half* b_base, int tid, int wm, int wn,
                                           int lr, int hh16) {
    if ((stp & 3) == 0) {
        int chunk = stp >> 2;
        cp_wait<STAGES - 2>();
        __syncthreads();
        int nc = chunk + STAGES - 1;
        if (nc < NKCH) load_stage(sb, a_base, b_base, nc, nc % STAGES, tid);
        cp_commit();  // empty-group commit in tail keeps wait counting uniform
    }
    uint32_t stA = sb + ((stp >> 2) % STAGES) * STAGE_BYTES;
    uint32_t stB = stA + A_BYTES;
    int kb = (stp & 3) * 32 + hh16;
#pragma unroll
    for (int mf = 0; mf < 4; mf++) {
        int row = wm + mf * 16 + lr;
        ldsm_x4(&af[mf * 4], stA + SWZ(row * 128 + kb));
    }
#pragma unroll
    for (int bi = 0; bi < 2; bi++) {
        int row = wn + bi * 16 + lr;
        ldsm_x4(&bf[bi * 4], stB + SWZ(row * 128 + kb));
    }
}

__device__ __forceinline__ void mma_step(float (&c)[4][4][4], const uint32_t (&af)[16],
                                         const uint32_t (&bf)[8]) {
#pragma unroll
    for (int mf = 0; mf < 4; mf++)
#pragma unroll
        for (int nf = 0; nf < 4; nf++) {
            const uint32_t* bb = &bf[(nf >> 1) * 4];
            mma16816(c[mf][nf], &af[mf * 4], bb[nf & 1], bb[2 + (nf & 1)]);
        }
}

__global__ __launch_bounds__(256, 2) void qlinear_gemm_kernel(float* __restrict__ C) {
    extern __shared__ char smem[];
    uint32_t sb = smem_u32(smem);
    int tid = threadIdx.x;
    int lid = tid & 31, wid = tid >> 5;
    int wm = (wid >> 2) * 64;   // warp M offset: 0 / 64
    int wn = (wid & 3) * 32;    // warp N offset: 0..96
    int lr = lid & 15;
    int hh16 = (lid >> 4) * 16;
    int bid = blockIdx.x;
    int mt = bid % MT;
    int nt = bid / MT;          // M fastest: A set L2-resident, B shared within wave

    const __half* a_base = g_xh + (size_t)mt * BM * IN_F;
    const __half* b_base = g_wh + (size_t)nt * BN * IN_F;

    // prologue: fill STAGES-1 stages (one commit group per chunk)
#pragma unroll
    for (int j = 0; j < STAGES - 1; j++) {
        load_stage(sb, a_base, b_base, j, j, tid);
        cp_commit();
    }

    float c[4][4][4];
#pragma unroll
    for (int i = 0; i < 4; i++)
#pragma unroll
        for (int j = 0; j < 4; j++)
#pragma unroll
            for (int q = 0; q < 4; q++) c[i][j][q] = 0.0f;

    uint32_t a0[16], b0[8], a1[16], b1[8];

    // preload step 0 (also waits chunk0 + issues chunk STAGES-1 refill)
    fetch_step(0, a0, b0, sb, a_base, b_base, tid, wm, wn, lr, hh16);

    // two-phase unrolled pipeline: fetch s+1 while mma s (buffer indices compile-time)
#pragma unroll 1
    for (int s = 0; s < NSTEP; s += 2) {
        fetch_step(s + 1, a1, b1, sb, a_base, b_base, tid, wm, wn, lr, hh16);
        mma_step(c, a0, b0);
        if (s + 2 < NSTEP)
            fetch_step(s + 2, a0, b0, sb, a_base, b_base, tid, wm, wn, lr, hh16);
        mma_step(c, a1, b1);
    }

    // epilogue: register accumulators -> gmem fp32
    int gid = lid >> 2, ctid = lid & 3;
    float* Cb = C + (size_t)(mt * BM + wm + gid) * OUT_F + nt * BN + wn + ctid * 2;
#pragma unroll
    for (int mf = 0; mf < 4; mf++) {
#pragma unroll
        for (int nf = 0; nf < 4; nf++) {
            float2 v0 = make_float2(c[mf][nf][0], c[mf][nf][1]);
            float2 v1 = make_float2(c[mf][nf][2], c[mf][nf][3]);
            *reinterpret_cast<float2*>(Cb + (size_t)(mf * 16) * OUT_F + nf * 8) = v0;
            *reinterpret_cast<float2*>(Cb + (size_t)(mf * 16 + 8) * OUT_F + nf * 8) = v1;
        }
    }
}

// ---------------- launch ----------------
extern "C" void kernel_launch(void* const* d_in, const int* in_sizes, int n_in,
                              void* d_out, int out_size) {
    (void)in_sizes; (void)n_in; (void)out_size;
    const float* x  = (const float*)d_in[0];
    const float* sx = (const float*)d_in[1];
    const float* w  = (const float*)d_in[2];
    const float* ws = (const float*)d_in[3];
    const float* wo = (const float*)d_in[4];
    float* out = (float*)d_out;

    cudaFuncSetAttribute(qlinear_gemm_kernel, cudaFuncAttributeMaxDynamicSharedMemorySize,
                         SMEM_TOTAL);

    dequant_x_kernel<<<TOKENS, 256>>>((const float4*)x, sx);
    dequant_w_kernel<<<OUT_F, 256>>>((const float4*)w, ws, wo);
    qlinear_gemm_kernel<<<MT * NT, 256, SMEM_TOTAL>>>(out);
}